// round 12
// baseline (speedup 1.0000x reference)
#include <cuda_runtime.h>

#define BATCH 4096
#define TT    512
#define IN    20
#define HID   51
#define NG    204
#define KDIM  71               // HID + IN
#define UPAD  52               // units padded to 52 (2% waste)
#define WROWD (UPAD * 8)       // 416 floats: per (k,u) 4 gates x {w,w}
#define SPB   32               // seqs per block (exact)
#define NBLK  (BATCH / SPB)    // 128 CTAs, 1 per SM
#define NTHR  480              // 13 matmul warps + 1 layer2 + 1 prefetch

// float offsets in dynamic smem
#define OFF_W   0                       // wdup[71][416]
#define OFF_HX  (KDIM * WROWD)          // two buffers [2][71][32]; rows 0..50 h, 51..70 x
#define HXBUF   (KDIM * 32)             // 2272 floats
#define OFF_W2  (OFF_HX + 2 * HXBUF)    // W_ih2 [4][51]
#define SMEM_FLOATS (OFF_W2 + NG)
#define SMEM_BYTES  (SMEM_FLOATS * 4)   // ~137 KB -> 1 CTA/SM

typedef unsigned long long ull;

__device__ __forceinline__ ull pack2(float v) {
    ull r; asm("mov.b64 %0, {%1, %1};" : "=l"(r) : "f"(v)); return r;
}
__device__ __forceinline__ ull fma2(ull a, ull b, ull c) {
    ull d; asm("fma.rn.f32x2 %0, %1, %2, %3;" : "=l"(d) : "l"(a), "l"(b), "l"(c)); return d;
}
__device__ __forceinline__ void unpack2(ull v, float& lo, float& hi) {
    asm("mov.b64 {%0, %1}, %2;" : "=f"(lo), "=f"(hi) : "l"(v));
}
// MUFU.TANH activations (validated in R11: rel_err 1.4e-6)
__device__ __forceinline__ float tanh_a(float x) {
    float y; asm("tanh.approx.f32 %0, %1;" : "=f"(y) : "f"(x)); return y;
}
__device__ __forceinline__ float fsig(float x)   { return fmaf(0.5f, tanh_a(0.5f * x), 0.5f); }
__device__ __forceinline__ float ftanh_(float x) { return tanh_a(x); }

__global__ __launch_bounds__(NTHR, 1) void lstm_v12_kernel(
    const float* __restrict__ x,
    const float* __restrict__ W_ih1, const float* __restrict__ W_hh1,
    const float* __restrict__ b_ih1, const float* __restrict__ b_hh1,
    const float* __restrict__ W_ih2, const float* __restrict__ W_hh2,
    const float* __restrict__ b_ih2, const float* __restrict__ b_hh2,
    const float* __restrict__ W_mu,  const float* __restrict__ b_mu,
    const float* __restrict__ W_lv,  const float* __restrict__ b_lv,
    float* __restrict__ out)
{
    extern __shared__ float sm[];
    const int tid = threadIdx.x;
    const int b32 = blockIdx.x * SPB;

    // ---------------- init ----------------
    // wdup[k][u*8 + g*2 + {0,1}] = W[g*51+u][k] duplicated; u >= 51 -> 0
    for (int i = tid; i < KDIM * WROWD; i += NTHR) {
        int k = i / WROWD, j = i % WROWD;
        int u = j >> 3, g = (j >> 1) & 3;
        float v = 0.f;
        if (u < HID) {
            int G = g * HID + u;
            v = (k < HID) ? W_hh1[G * HID + k] : W_ih1[G * IN + (k - HID)];
        }
        sm[OFF_W + i] = v;
    }
    for (int i = tid; i < 2 * HXBUF; i += NTHR) sm[OFF_HX + i] = 0.f;
    for (int i = tid; i < NG; i += NTHR) sm[OFF_W2 + i] = W_ih2[i];   // [4][51]
    __syncthreads();
    if (tid >= 448) {   // prefetch warp stages x(0) -> buf0 rows 51..70
        int s = tid - 448;
        const float4* xp = reinterpret_cast<const float4*>(&x[((size_t)(b32 + s) * TT) * IN]);
        #pragma unroll
        for (int q = 0; q < 5; q++) {
            float4 v = xp[q];
            sm[OFF_HX + (HID + 4*q + 0) * 32 + s] = v.x;
            sm[OFF_HX + (HID + 4*q + 1) * 32 + s] = v.y;
            sm[OFF_HX + (HID + 4*q + 2) * 32 + s] = v.z;
            sm[OFF_HX + (HID + 4*q + 3) * 32 + s] = v.w;
        }
    }

    // matmul threads 0..415: u = tid>>3 (0..51), seq-quad q = tid&7 (seqs 4q..4q+3)
    const int u = tid >> 3;
    const int q = tid & 7;
    ull bp[4] = {0ULL, 0ULL, 0ULL, 0ULL};
    if (tid < 416 && u < HID) {
        #pragma unroll
        for (int g = 0; g < 4; g++)
            bp[g] = pack2(b_ih1[g * HID + u] + b_hh1[g * HID + u]);
    }
    float c1[4] = {0.f, 0.f, 0.f, 0.f};

    // layer-2 warp: tid 416..447, seq = tid-416
    const int l2s = tid - 416;
    float c2 = 0.f, h2 = 0.f, sum_h2 = 0.f;
    float l2b[4] = {0,0,0,0}, l2w[4] = {0,0,0,0};
    if (tid >= 416 && tid < 448) {
        #pragma unroll
        for (int g = 0; g < 4; g++) { l2b[g] = b_ih2[g] + b_hh2[g]; l2w[g] = W_hh2[g]; }
    }
    // prefetch warp: tid 448..479, seq = tid-448
    const int xs = tid - 448;
    __syncthreads();

    #pragma unroll 1
    for (int t = 0; t < TT; t++) {
        const float* A = &sm[OFF_HX + (t & 1) * HXBUF];          // h(t-1), x(t)
        float*       B = &sm[OFF_HX + ((t + 1) & 1) * HXBUF];    // h(t), x(t+1)

        if (tid < 416) {
            // ---- unit u, seqs 4q..4q+3: per k 3 LDS.128 + 8 FFMA2, 0 MOV ----
            ull a[8];   // a[g*2+p], p = seq pair
            #pragma unroll
            for (int g = 0; g < 4; g++) { a[g*2] = bp[g]; a[g*2+1] = bp[g]; }
            const float* wb = &sm[OFF_W + u * 8];
            const float* hb = A + q * 4;
            #pragma unroll
            for (int k = 0; k < KDIM; k++) {
                ulonglong2 w01 = *reinterpret_cast<const ulonglong2*>(wb + k * WROWD);     // {wi,wi},{wf,wf}
                ulonglong2 w23 = *reinterpret_cast<const ulonglong2*>(wb + k * WROWD + 4); // {wg,wg},{wo,wo}
                ulonglong2 hp  = *reinterpret_cast<const ulonglong2*>(hb + k * 32);        // {h0,h1},{h2,h3}
                a[0] = fma2(w01.x, hp.x, a[0]); a[1] = fma2(w01.x, hp.y, a[1]);
                a[2] = fma2(w01.y, hp.x, a[2]); a[3] = fma2(w01.y, hp.y, a[3]);
                a[4] = fma2(w23.x, hp.x, a[4]); a[5] = fma2(w23.x, hp.y, a[5]);
                a[6] = fma2(w23.y, hp.x, a[6]); a[7] = fma2(w23.y, hp.y, a[7]);
            }
            // ---- in-register activations; write h(t) quad to B ----
            if (u < HID) {
                float hv[4];
                #pragma unroll
                for (int p = 0; p < 2; p++) {
                    float i0,i1,f0,f1,g0,g1,o0,o1;
                    unpack2(a[0 + p], i0, i1);
                    unpack2(a[2 + p], f0, f1);
                    unpack2(a[4 + p], g0, g1);
                    unpack2(a[6 + p], o0, o1);
                    float ca = fsig(f0) * c1[2*p]     + fsig(i0) * ftanh_(g0);
                    c1[2*p] = ca;     hv[2*p]     = fsig(o0) * ftanh_(ca);
                    float cb = fsig(f1) * c1[2*p + 1] + fsig(i1) * ftanh_(g1);
                    c1[2*p+1] = cb;   hv[2*p + 1] = fsig(o1) * ftanh_(cb);
                }
                *reinterpret_cast<float4*>(B + u * 32 + q * 4) = make_float4(hv[0], hv[1], hv[2], hv[3]);
            }
        } else if (tid < 448) {
            // layer 2 on h(t-1) in A
            if (t > 0) {
                float zi = 0.f, zf = 0.f, zg = 0.f, zo = 0.f;
                #pragma unroll
                for (int k = 0; k < HID; k++) {
                    float hvv = A[k * 32 + l2s];
                    zi += sm[OFF_W2 +          k] * hvv;
                    zf += sm[OFF_W2 + HID    + k] * hvv;
                    zg += sm[OFF_W2 + 2*HID  + k] * hvv;
                    zo += sm[OFF_W2 + 3*HID  + k] * hvv;
                }
                float i2 = fsig  (zi + l2b[0] + l2w[0] * h2);
                float f2 = fsig  (zf + l2b[1] + l2w[1] * h2);
                float g2v= ftanh_(zg + l2b[2] + l2w[2] * h2);
                float o2 = fsig  (zo + l2b[3] + l2w[3] * h2);
                c2 = f2 * c2 + i2 * g2v;
                h2 = o2 * ftanh_(c2);
                sum_h2 += h2;
            }
        } else {
            // x-prefetch warp: load x(t+1), store into B rows 51..70
            if (t + 1 < TT) {
                float4 xv[5];
                const float4* xp = reinterpret_cast<const float4*>(
                    &x[((size_t)(b32 + xs) * TT + t + 1) * IN]);
                #pragma unroll
                for (int qq = 0; qq < 5; qq++) xv[qq] = xp[qq];
                #pragma unroll
                for (int qq = 0; qq < 5; qq++) {
                    B[(HID + 4*qq + 0) * 32 + xs] = xv[qq].x;
                    B[(HID + 4*qq + 1) * 32 + xs] = xv[qq].y;
                    B[(HID + 4*qq + 2) * 32 + xs] = xv[qq].z;
                    B[(HID + 4*qq + 3) * 32 + xs] = xv[qq].w;
                }
            }
        }
        __syncthreads();
    }

    // ---------- final layer-2 step on h(T-1) + epilogue ----------
    if (tid >= 416 && tid < 448) {
        const float* A = &sm[OFF_HX + (TT & 1) * HXBUF];
        float zi = 0.f, zf = 0.f, zg = 0.f, zo = 0.f;
        #pragma unroll
        for (int k = 0; k < HID; k++) {
            float hvv = A[k * 32 + l2s];
            zi += sm[OFF_W2 +          k] * hvv;
            zf += sm[OFF_W2 + HID    + k] * hvv;
            zg += sm[OFF_W2 + 2*HID  + k] * hvv;
            zo += sm[OFF_W2 + 3*HID  + k] * hvv;
        }
        float i2 = fsig  (zi + l2b[0] + l2w[0] * h2);
        float f2 = fsig  (zf + l2b[1] + l2w[1] * h2);
        float g2v= ftanh_(zg + l2b[2] + l2w[2] * h2);
        float o2 = fsig  (zo + l2b[3] + l2w[3] * h2);
        c2 = f2 * c2 + i2 * g2v;
        h2 = o2 * ftanh_(c2);
        sum_h2 += h2;

        float agg = sum_h2 * (1.0f / TT);
        float mu  = W_mu[0] * agg + b_mu[0];
        float lv  = W_lv[0] * agg + b_lv[0];
        float sg  = __expf(0.5f * lv);
        int b = b32 + l2s;
        out[b]           = mu - 1.96f * sg;
        out[BATCH + b]   = mu;
        out[2*BATCH + b] = mu + 1.96f * sg;
        out[3*BATCH + b] = lv;
    }
}

extern "C" void kernel_launch(void* const* d_in, const int* in_sizes, int n_in,
                              void* d_out, int out_size) {
    const float* x     = (const float*)d_in[0];
    const float* W_ih1 = (const float*)d_in[1];
    const float* W_hh1 = (const float*)d_in[2];
    const float* b_ih1 = (const float*)d_in[3];
    const float* b_hh1 = (const float*)d_in[4];
    const float* W_ih2 = (const float*)d_in[5];
    const float* W_hh2 = (const float*)d_in[6];
    const float* b_ih2 = (const float*)d_in[7];
    const float* b_hh2 = (const float*)d_in[8];
    const float* W_mu  = (const float*)d_in[9];
    const float* b_mu  = (const float*)d_in[10];
    const float* W_lv  = (const float*)d_in[11];
    const float* b_lv  = (const float*)d_in[12];
    float* out = (float*)d_out;

    cudaFuncSetAttribute(lstm_v12_kernel,
                         cudaFuncAttributeMaxDynamicSharedMemorySize, SMEM_BYTES);
    lstm_v12_kernel<<<NBLK, NTHR, SMEM_BYTES>>>(x, W_ih1, W_hh1, b_ih1, b_hh1,
                                                W_ih2, W_hh2, b_ih2, b_hh2,
                                                W_mu, b_mu, W_lv, b_lv, out);
}

// round 13
// speedup vs baseline: 1.0007x; 1.0007x over previous
#include <cuda_runtime.h>

#define BATCH 4096
#define TT    512
#define IN    20
#define HID   51
#define NG    204
#define KDIM  71               // HID + IN
#define UPAD  52               // units padded to 52 (2% waste)
#define WROWD (UPAD * 8)       // 416 floats: per (k,u) 4 gates x {w,w}
#define SPB   32               // seqs per block (exact)
#define NBLK  (BATCH / SPB)    // 128 CTAs, 1 per SM
#define NTHR  480              // 13 matmul warps + 1 layer2 + 1 prefetch

// float offsets in dynamic smem
#define OFF_W   0                       // wdup[71][416]
#define OFF_HX  (KDIM * WROWD)          // two buffers [2][71][32]; rows 0..50 h, 51..70 x
#define HXBUF   (KDIM * 32)             // 2272 floats
#define OFF_W2  (OFF_HX + 2 * HXBUF)    // W_ih2 [4][51]
#define SMEM_FLOATS (OFF_W2 + NG)
#define SMEM_BYTES  (SMEM_FLOATS * 4)   // ~137 KB -> 1 CTA/SM

typedef unsigned long long ull;

__device__ __forceinline__ ull pack2(float v) {
    ull r; asm("mov.b64 %0, {%1, %1};" : "=l"(r) : "f"(v)); return r;
}
__device__ __forceinline__ ull fma2(ull a, ull b, ull c) {
    ull d; asm("fma.rn.f32x2 %0, %1, %2, %3;" : "=l"(d) : "l"(a), "l"(b), "l"(c)); return d;
}
__device__ __forceinline__ void unpack2(ull v, float& lo, float& hi) {
    asm("mov.b64 {%0, %1}, %2;" : "=f"(lo), "=f"(hi) : "l"(v));
}
// MUFU.TANH activations (validated in R11: rel_err 1.4e-6)
__device__ __forceinline__ float tanh_a(float x) {
    float y; asm("tanh.approx.f32 %0, %1;" : "=f"(y) : "f"(x)); return y;
}
__device__ __forceinline__ float fsig(float x)   { return fmaf(0.5f, tanh_a(0.5f * x), 0.5f); }
__device__ __forceinline__ float ftanh_(float x) { return tanh_a(x); }

__global__ __launch_bounds__(NTHR, 1) void lstm_v12_kernel(
    const float* __restrict__ x,
    const float* __restrict__ W_ih1, const float* __restrict__ W_hh1,
    const float* __restrict__ b_ih1, const float* __restrict__ b_hh1,
    const float* __restrict__ W_ih2, const float* __restrict__ W_hh2,
    const float* __restrict__ b_ih2, const float* __restrict__ b_hh2,
    const float* __restrict__ W_mu,  const float* __restrict__ b_mu,
    const float* __restrict__ W_lv,  const float* __restrict__ b_lv,
    float* __restrict__ out)
{
    extern __shared__ float sm[];
    const int tid = threadIdx.x;
    const int b32 = blockIdx.x * SPB;

    // ---------------- init ----------------
    // wdup[k][u*8 + g*2 + {0,1}] = W[g*51+u][k] duplicated; u >= 51 -> 0
    for (int i = tid; i < KDIM * WROWD; i += NTHR) {
        int k = i / WROWD, j = i % WROWD;
        int u = j >> 3, g = (j >> 1) & 3;
        float v = 0.f;
        if (u < HID) {
            int G = g * HID + u;
            v = (k < HID) ? W_hh1[G * HID + k] : W_ih1[G * IN + (k - HID)];
        }
        sm[OFF_W + i] = v;
    }
    for (int i = tid; i < 2 * HXBUF; i += NTHR) sm[OFF_HX + i] = 0.f;
    for (int i = tid; i < NG; i += NTHR) sm[OFF_W2 + i] = W_ih2[i];   // [4][51]
    __syncthreads();
    if (tid >= 448) {   // prefetch warp stages x(0) -> buf0 rows 51..70
        int s = tid - 448;
        const float4* xp = reinterpret_cast<const float4*>(&x[((size_t)(b32 + s) * TT) * IN]);
        #pragma unroll
        for (int q = 0; q < 5; q++) {
            float4 v = xp[q];
            sm[OFF_HX + (HID + 4*q + 0) * 32 + s] = v.x;
            sm[OFF_HX + (HID + 4*q + 1) * 32 + s] = v.y;
            sm[OFF_HX + (HID + 4*q + 2) * 32 + s] = v.z;
            sm[OFF_HX + (HID + 4*q + 3) * 32 + s] = v.w;
        }
    }

    // matmul threads 0..415: u = tid>>3 (0..51), seq-quad q = tid&7 (seqs 4q..4q+3)
    const int u = tid >> 3;
    const int q = tid & 7;
    ull bp[4] = {0ULL, 0ULL, 0ULL, 0ULL};
    if (tid < 416 && u < HID) {
        #pragma unroll
        for (int g = 0; g < 4; g++)
            bp[g] = pack2(b_ih1[g * HID + u] + b_hh1[g * HID + u]);
    }
    float c1[4] = {0.f, 0.f, 0.f, 0.f};

    // layer-2 warp: tid 416..447, seq = tid-416
    const int l2s = tid - 416;
    float c2 = 0.f, h2 = 0.f, sum_h2 = 0.f;
    float l2b[4] = {0,0,0,0}, l2w[4] = {0,0,0,0};
    if (tid >= 416 && tid < 448) {
        #pragma unroll
        for (int g = 0; g < 4; g++) { l2b[g] = b_ih2[g] + b_hh2[g]; l2w[g] = W_hh2[g]; }
    }
    // prefetch warp: tid 448..479, seq = tid-448
    const int xs = tid - 448;
    __syncthreads();

    #pragma unroll 1
    for (int t = 0; t < TT; t++) {
        const float* A = &sm[OFF_HX + (t & 1) * HXBUF];          // h(t-1), x(t)
        float*       B = &sm[OFF_HX + ((t + 1) & 1) * HXBUF];    // h(t), x(t+1)

        if (tid < 416) {
            // ---- unit u, seqs 4q..4q+3: per k 3 LDS.128 + 8 FFMA2, 0 MOV ----
            ull a[8];   // a[g*2+p], p = seq pair
            #pragma unroll
            for (int g = 0; g < 4; g++) { a[g*2] = bp[g]; a[g*2+1] = bp[g]; }
            const float* wb = &sm[OFF_W + u * 8];
            const float* hb = A + q * 4;
            #pragma unroll
            for (int k = 0; k < KDIM; k++) {
                ulonglong2 w01 = *reinterpret_cast<const ulonglong2*>(wb + k * WROWD);     // {wi,wi},{wf,wf}
                ulonglong2 w23 = *reinterpret_cast<const ulonglong2*>(wb + k * WROWD + 4); // {wg,wg},{wo,wo}
                ulonglong2 hp  = *reinterpret_cast<const ulonglong2*>(hb + k * 32);        // {h0,h1},{h2,h3}
                a[0] = fma2(w01.x, hp.x, a[0]); a[1] = fma2(w01.x, hp.y, a[1]);
                a[2] = fma2(w01.y, hp.x, a[2]); a[3] = fma2(w01.y, hp.y, a[3]);
                a[4] = fma2(w23.x, hp.x, a[4]); a[5] = fma2(w23.x, hp.y, a[5]);
                a[6] = fma2(w23.y, hp.x, a[6]); a[7] = fma2(w23.y, hp.y, a[7]);
            }
            // ---- in-register activations; write h(t) quad to B ----
            if (u < HID) {
                float hv[4];
                #pragma unroll
                for (int p = 0; p < 2; p++) {
                    float i0,i1,f0,f1,g0,g1,o0,o1;
                    unpack2(a[0 + p], i0, i1);
                    unpack2(a[2 + p], f0, f1);
                    unpack2(a[4 + p], g0, g1);
                    unpack2(a[6 + p], o0, o1);
                    float ca = fsig(f0) * c1[2*p]     + fsig(i0) * ftanh_(g0);
                    c1[2*p] = ca;     hv[2*p]     = fsig(o0) * ftanh_(ca);
                    float cb = fsig(f1) * c1[2*p + 1] + fsig(i1) * ftanh_(g1);
                    c1[2*p+1] = cb;   hv[2*p + 1] = fsig(o1) * ftanh_(cb);
                }
                *reinterpret_cast<float4*>(B + u * 32 + q * 4) = make_float4(hv[0], hv[1], hv[2], hv[3]);
            }
        } else if (tid < 448) {
            // layer 2 on h(t-1) in A
            if (t > 0) {
                float zi = 0.f, zf = 0.f, zg = 0.f, zo = 0.f;
                #pragma unroll
                for (int k = 0; k < HID; k++) {
                    float hvv = A[k * 32 + l2s];
                    zi += sm[OFF_W2 +          k] * hvv;
                    zf += sm[OFF_W2 + HID    + k] * hvv;
                    zg += sm[OFF_W2 + 2*HID  + k] * hvv;
                    zo += sm[OFF_W2 + 3*HID  + k] * hvv;
                }
                float i2 = fsig  (zi + l2b[0] + l2w[0] * h2);
                float f2 = fsig  (zf + l2b[1] + l2w[1] * h2);
                float g2v= ftanh_(zg + l2b[2] + l2w[2] * h2);
                float o2 = fsig  (zo + l2b[3] + l2w[3] * h2);
                c2 = f2 * c2 + i2 * g2v;
                h2 = o2 * ftanh_(c2);
                sum_h2 += h2;
            }
        } else {
            // x-prefetch warp: load x(t+1), store into B rows 51..70
            if (t + 1 < TT) {
                float4 xv[5];
                const float4* xp = reinterpret_cast<const float4*>(
                    &x[((size_t)(b32 + xs) * TT + t + 1) * IN]);
                #pragma unroll
                for (int qq = 0; qq < 5; qq++) xv[qq] = xp[qq];
                #pragma unroll
                for (int qq = 0; qq < 5; qq++) {
                    B[(HID + 4*qq + 0) * 32 + xs] = xv[qq].x;
                    B[(HID + 4*qq + 1) * 32 + xs] = xv[qq].y;
                    B[(HID + 4*qq + 2) * 32 + xs] = xv[qq].z;
                    B[(HID + 4*qq + 3) * 32 + xs] = xv[qq].w;
                }
            }
        }
        __syncthreads();
    }

    // ---------- final layer-2 step on h(T-1) + epilogue ----------
    if (tid >= 416 && tid < 448) {
        const float* A = &sm[OFF_HX + (TT & 1) * HXBUF];
        float zi = 0.f, zf = 0.f, zg = 0.f, zo = 0.f;
        #pragma unroll
        for (int k = 0; k < HID; k++) {
            float hvv = A[k * 32 + l2s];
            zi += sm[OFF_W2 +          k] * hvv;
            zf += sm[OFF_W2 + HID    + k] * hvv;
            zg += sm[OFF_W2 + 2*HID  + k] * hvv;
            zo += sm[OFF_W2 + 3*HID  + k] * hvv;
        }
        float i2 = fsig  (zi + l2b[0] + l2w[0] * h2);
        float f2 = fsig  (zf + l2b[1] + l2w[1] * h2);
        float g2v= ftanh_(zg + l2b[2] + l2w[2] * h2);
        float o2 = fsig  (zo + l2b[3] + l2w[3] * h2);
        c2 = f2 * c2 + i2 * g2v;
        h2 = o2 * ftanh_(c2);
        sum_h2 += h2;

        float agg = sum_h2 * (1.0f / TT);
        float mu  = W_mu[0] * agg + b_mu[0];
        float lv  = W_lv[0] * agg + b_lv[0];
        float sg  = __expf(0.5f * lv);
        int b = b32 + l2s;
        out[b]           = mu - 1.96f * sg;
        out[BATCH + b]   = mu;
        out[2*BATCH + b] = mu + 1.96f * sg;
        out[3*BATCH + b] = lv;
    }
}

extern "C" void kernel_launch(void* const* d_in, const int* in_sizes, int n_in,
                              void* d_out, int out_size) {
    const float* x     = (const float*)d_in[0];
    const float* W_ih1 = (const float*)d_in[1];
    const float* W_hh1 = (const float*)d_in[2];
    const float* b_ih1 = (const float*)d_in[3];
    const float* b_hh1 = (const float*)d_in[4];
    const float* W_ih2 = (const float*)d_in[5];
    const float* W_hh2 = (const float*)d_in[6];
    const float* b_ih2 = (const float*)d_in[7];
    const float* b_hh2 = (const float*)d_in[8];
    const float* W_mu  = (const float*)d_in[9];
    const float* b_mu  = (const float*)d_in[10];
    const float* W_lv  = (const float*)d_in[11];
    const float* b_lv  = (const float*)d_in[12];
    float* out = (float*)d_out;

    cudaFuncSetAttribute(lstm_v12_kernel,
                         cudaFuncAttributeMaxDynamicSharedMemorySize, SMEM_BYTES);
    lstm_v12_kernel<<<NBLK, NTHR, SMEM_BYTES>>>(x, W_ih1, W_hh1, b_ih1, b_hh1,
                                                W_ih2, W_hh2, b_ih2, b_hh2,
                                                W_mu, b_mu, W_lv, b_lv, out);
}

// round 14
// speedup vs baseline: 1.3597x; 1.3587x over previous
#include <cuda_runtime.h>

#define BATCH 4096
#define TT    512
#define IN    20
#define HID   51
#define NG    204
#define KDIM  71              // HID + IN
#define WROW  204             // interleaved weight row [u*4+g], unpadded
#define SPB   16              // layout width
#define NBLK  296             // 148 SMs x 2 CTAs; 248x14 + 48x13 = 4096 seqs
#define NTHR  160             // warps 0-2 fat matmul, warp 3 remainder, warp 4 helper

// float offsets in dynamic smem
#define OFF_W   0                         // w_il[71][204]
#define OFF_HX  (KDIM * WROW)             // two buffers [2][71][16]; rows 0..50 h, 51..70 x
#define HXBUF   (KDIM * 16)               // 1136 floats
#define OFF_W2  (OFF_HX + 2 * HXBUF)      // W_ih2 [4][51]
#define SMEM_FLOATS (OFF_W2 + NG)
#define SMEM_BYTES  (SMEM_FLOATS * 4)     // ~68 KB -> 2 CTAs/SM

typedef unsigned long long ull;

__device__ __forceinline__ ull pack2(float v) {
    ull r; asm("mov.b64 %0, {%1, %1};" : "=l"(r) : "f"(v)); return r;
}
__device__ __forceinline__ ull fma2(ull a, ull b, ull c) {
    ull d; asm("fma.rn.f32x2 %0, %1, %2, %3;" : "=l"(d) : "l"(a), "l"(b), "l"(c)); return d;
}
__device__ __forceinline__ void unpack2(ull v, float& lo, float& hi) {
    asm("mov.b64 {%0, %1}, %2;" : "=f"(lo), "=f"(hi) : "l"(v));
}
// MUFU.TANH activations (validated R11: rel_err 1.36e-6)
__device__ __forceinline__ float tanh_a(float x) {
    float y; asm("tanh.approx.f32 %0, %1;" : "=f"(y) : "f"(x)); return y;
}
__device__ __forceinline__ float fsig(float x)   { return fmaf(0.5f, tanh_a(0.5f * x), 0.5f); }
__device__ __forceinline__ float ftanh_(float x) { return tanh_a(x); }

__global__ __launch_bounds__(NTHR, 2) void lstm_v14_kernel(
    const float* __restrict__ x,
    const float* __restrict__ W_ih1, const float* __restrict__ W_hh1,
    const float* __restrict__ b_ih1, const float* __restrict__ b_hh1,
    const float* __restrict__ W_ih2, const float* __restrict__ W_hh2,
    const float* __restrict__ b_ih2, const float* __restrict__ b_hh2,
    const float* __restrict__ W_mu,  const float* __restrict__ b_mu,
    const float* __restrict__ W_lv,  const float* __restrict__ b_lv,
    float* __restrict__ out)
{
    extern __shared__ float sm[];
    const int tid = threadIdx.x;

    // balanced seq assignment: first 248 CTAs take 14 seqs, last 48 take 13
    int start, cnt;
    if (blockIdx.x < 248) { start = blockIdx.x * 14;              cnt = 14; }
    else                  { start = 3472 + (blockIdx.x - 248)*13; cnt = 13; }

    // ---------------- init ----------------
    // interleaved: w_il[k][u*4+g], g: 0=i,1=f,2=g,3=o ; source gate row G = g*51+u
    for (int i = tid; i < KDIM * WROW; i += NTHR) {
        int k = i / WROW, j = i % WROW;
        int u = j >> 2, g = j & 3;
        int G = g * HID + u;
        sm[OFF_W + i] = (k < HID) ? W_hh1[G * HID + k] : W_ih1[G * IN + (k - HID)];
    }
    for (int i = tid; i < 2 * HXBUF; i += NTHR) sm[OFF_HX + i] = 0.f;   // zero both buffers
    for (int i = tid; i < NG; i += NTHR) sm[OFF_W2 + i] = W_ih2[i];
    __syncthreads();
    if (tid < cnt) {   // x(0) -> buf0 rows 51..70
        const float4* xp = reinterpret_cast<const float4*>(&x[((size_t)(start + tid) * TT) * IN]);
        #pragma unroll
        for (int q = 0; q < 5; q++) {
            float4 v = xp[q];
            sm[OFF_HX + (HID + 4*q + 0) * 16 + tid] = v.x;
            sm[OFF_HX + (HID + 4*q + 1) * 16 + tid] = v.y;
            sm[OFF_HX + (HID + 4*q + 2) * 16 + tid] = v.z;
            sm[OFF_HX + (HID + 4*q + 3) * 16 + tid] = v.w;
        }
    }

    // ---- warps 0..2 (tid<96): fat tile, unit u = tid>>1 (0..47), seq-half sh8 ----
    const int u   = tid >> 1;
    const int sh8 = (tid & 1) << 3;
    ull bp[4] = {0ULL, 0ULL, 0ULL, 0ULL};
    if (tid < 96) {
        #pragma unroll
        for (int g = 0; g < 4; g++)
            bp[g] = pack2(b_ih1[g * HID + u] + b_hh1[g * HID + u]);
    }
    // ---- warp 3 (tid 96..127), lanes 0..23: remainder units 48..50 ----
    const int lane3 = tid - 96;
    const bool w3m = (tid >= 96 && tid < 128 && lane3 < 24);
    const int u3 = 48 + (lane3 >> 3);          // 48..50
    const int p3 = (lane3 >> 2) & 1;           // gate-pair: 0 -> (i,f), 1 -> (g,o)
    const int q3 = lane3 & 3;                  // seq-quad: seqs 4q3..4q3+3
    ull b3lo = 0ULL, b3hi = 0ULL;
    if (w3m) {
        int glo = 2 * p3, ghi = 2 * p3 + 1;
        b3lo = pack2(b_ih1[glo * HID + u3] + b_hh1[glo * HID + u3]);
        b3hi = pack2(b_ih1[ghi * HID + u3] + b_hh1[ghi * HID + u3]);
    }
    float c1[8] = {0.f,0.f,0.f,0.f,0.f,0.f,0.f,0.f};

    // ---- warp 4 helper (tid 128..159): seq hs; x prefetch + layer 2 ----
    const int hs = tid - 128;
    const bool hlp = (hs >= 0 && hs < cnt);
    float c2 = 0.f, h2 = 0.f, sum_h2 = 0.f;
    float l2b[4] = {0,0,0,0}, l2w[4] = {0,0,0,0};
    if (hlp) {
        #pragma unroll
        for (int g = 0; g < 4; g++) { l2b[g] = b_ih2[g] + b_hh2[g]; l2w[g] = W_hh2[g]; }
    }
    __syncthreads();

    #pragma unroll 1
    for (int t = 0; t < TT; t++) {
        const float* A = &sm[OFF_HX + (t & 1) * HXBUF];          // h(t-1), x(t)
        float*       B = &sm[OFF_HX + ((t + 1) & 1) * HXBUF];    // h(t), x(t+1)

        if (tid < 96) {
            // ---- fat tile: unit u, 8 seqs, all 4 gates ----
            ull a[16];   // a[g*4+p], p -> seq pairs
            #pragma unroll
            for (int g = 0; g < 4; g++) {
                a[g*4+0] = bp[g]; a[g*4+1] = bp[g]; a[g*4+2] = bp[g]; a[g*4+3] = bp[g];
            }
            const float* wb = &sm[OFF_W + u * 4];
            const float* hb = A + sh8;
            #pragma unroll
            for (int k = 0; k < KDIM; k++) {
                float4 w4 = *reinterpret_cast<const float4*>(wb + k * WROW);
                ulonglong2 h0 = *reinterpret_cast<const ulonglong2*>(hb + k * 16);
                ulonglong2 h1 = *reinterpret_cast<const ulonglong2*>(hb + k * 16 + 4);
                ull wi = pack2(w4.x), wf = pack2(w4.y), wg = pack2(w4.z), wo = pack2(w4.w);
                a[0]  = fma2(wi, h0.x, a[0]);  a[1]  = fma2(wi, h0.y, a[1]);
                a[2]  = fma2(wi, h1.x, a[2]);  a[3]  = fma2(wi, h1.y, a[3]);
                a[4]  = fma2(wf, h0.x, a[4]);  a[5]  = fma2(wf, h0.y, a[5]);
                a[6]  = fma2(wf, h1.x, a[6]);  a[7]  = fma2(wf, h1.y, a[7]);
                a[8]  = fma2(wg, h0.x, a[8]);  a[9]  = fma2(wg, h0.y, a[9]);
                a[10] = fma2(wg, h1.x, a[10]); a[11] = fma2(wg, h1.y, a[11]);
                a[12] = fma2(wo, h0.x, a[12]); a[13] = fma2(wo, h0.y, a[13]);
                a[14] = fma2(wo, h1.x, a[14]); a[15] = fma2(wo, h1.y, a[15]);
            }
            // in-register activations, write h(t) to B
            float hv[8];
            #pragma unroll
            for (int p = 0; p < 4; p++) {
                float i0,i1,f0,f1,g0,g1,o0,o1;
                unpack2(a[p],      i0, i1);
                unpack2(a[4 + p],  f0, f1);
                unpack2(a[8 + p],  g0, g1);
                unpack2(a[12 + p], o0, o1);
                float ca = fsig(f0) * c1[2*p]     + fsig(i0) * ftanh_(g0);
                c1[2*p] = ca;     hv[2*p]     = fsig(o0) * ftanh_(ca);
                float cb = fsig(f1) * c1[2*p + 1] + fsig(i1) * ftanh_(g1);
                c1[2*p+1] = cb;   hv[2*p + 1] = fsig(o1) * ftanh_(cb);
            }
            *reinterpret_cast<float4*>(B + u * 16 + sh8)     = make_float4(hv[0], hv[1], hv[2], hv[3]);
            *reinterpret_cast<float4*>(B + u * 16 + sh8 + 4) = make_float4(hv[4], hv[5], hv[6], hv[7]);
        } else if (tid < 128) {
            // ---- warp 3: fine tile for units 48..50 (lanes 0..23) ----
            if (w3m) {
                ull a0 = b3lo, a1 = b3lo, a2 = b3hi, a3 = b3hi;
                const float* wb3 = &sm[OFF_W + u3 * 4 + p3 * 2];
                const float* hb3 = A + q3 * 4;
                #pragma unroll
                for (int k = 0; k < KDIM; k++) {
                    float2 wv = *reinterpret_cast<const float2*>(wb3 + k * WROW);
                    ulonglong2 hp = *reinterpret_cast<const ulonglong2*>(hb3 + k * 16);
                    ull wlo = pack2(wv.x), whi = pack2(wv.y);
                    a0 = fma2(wlo, hp.x, a0); a1 = fma2(wlo, hp.y, a1);
                    a2 = fma2(whi, hp.x, a2); a3 = fma2(whi, hp.y, a3);
                }
                // exchange gate-pairs with partner lane (xor 4): p0 gets (g,o), p1 gets (i,f)
                ull pa0 = __shfl_xor_sync(0x00FFFFFFu, a0, 4);
                ull pa1 = __shfl_xor_sync(0x00FFFFFFu, a1, 4);
                ull pa2 = __shfl_xor_sync(0x00FFFFFFu, a2, 4);
                ull pa3 = __shfl_xor_sync(0x00FFFFFFu, a3, 4);
                if (p3 == 0) {
                    // this lane: i = (a0,a1), f = (a2,a3); partner: g = (pa0,pa1), o = (pa2,pa3)
                    float hv[4];
                    #pragma unroll
                    for (int p = 0; p < 2; p++) {
                        float i0,i1,f0,f1,g0,g1,o0,o1;
                        unpack2(p ? a1  : a0,  i0, i1);
                        unpack2(p ? a3  : a2,  f0, f1);
                        unpack2(p ? pa1 : pa0, g0, g1);
                        unpack2(p ? pa3 : pa2, o0, o1);
                        float ca = fsig(f0) * c1[2*p]     + fsig(i0) * ftanh_(g0);
                        c1[2*p] = ca;     hv[2*p]     = fsig(o0) * ftanh_(ca);
                        float cb = fsig(f1) * c1[2*p + 1] + fsig(i1) * ftanh_(g1);
                        c1[2*p+1] = cb;   hv[2*p + 1] = fsig(o1) * ftanh_(cb);
                    }
                    *reinterpret_cast<float4*>(B + u3 * 16 + q3 * 4) =
                        make_float4(hv[0], hv[1], hv[2], hv[3]);
                }
            }
        } else if (hlp) {
            // fire x(t+1) loads early
            float4 xv[5];
            if (t + 1 < TT) {
                const float4* xp = reinterpret_cast<const float4*>(
                    &x[((size_t)(start + hs) * TT + t + 1) * IN]);
                #pragma unroll
                for (int q = 0; q < 5; q++) xv[q] = xp[q];
            }
            // layer 2 on h(t-1) in A
            if (t > 0) {
                float zi = 0.f, zf = 0.f, zg = 0.f, zo = 0.f;
                #pragma unroll
                for (int k = 0; k < HID; k++) {
                    float hvv = A[k * 16 + hs];
                    zi += sm[OFF_W2 +          k] * hvv;
                    zf += sm[OFF_W2 + HID    + k] * hvv;
                    zg += sm[OFF_W2 + 2*HID  + k] * hvv;
                    zo += sm[OFF_W2 + 3*HID  + k] * hvv;
                }
                float i2 = fsig  (zi + l2b[0] + l2w[0] * h2);
                float f2 = fsig  (zf + l2b[1] + l2w[1] * h2);
                float g2v= ftanh_(zg + l2b[2] + l2w[2] * h2);
                float o2 = fsig  (zo + l2b[3] + l2w[3] * h2);
                c2 = f2 * c2 + i2 * g2v;
                h2 = o2 * ftanh_(c2);
                sum_h2 += h2;
            }
            // store x(t+1) into B rows 51..70
            if (t + 1 < TT) {
                #pragma unroll
                for (int q = 0; q < 5; q++) {
                    B[(HID + 4*q + 0) * 16 + hs] = xv[q].x;
                    B[(HID + 4*q + 1) * 16 + hs] = xv[q].y;
                    B[(HID + 4*q + 2) * 16 + hs] = xv[q].z;
                    B[(HID + 4*q + 3) * 16 + hs] = xv[q].w;
                }
            }
        }
        __syncthreads();
    }

    // ---------- final layer-2 step on h(T-1) + epilogue ----------
    if (hlp) {
        const float* A = &sm[OFF_HX + (TT & 1) * HXBUF];
        float zi = 0.f, zf = 0.f, zg = 0.f, zo = 0.f;
        #pragma unroll
        for (int k = 0; k < HID; k++) {
            float hvv = A[k * 16 + hs];
            zi += sm[OFF_W2 +          k] * hvv;
            zf += sm[OFF_W2 + HID    + k] * hvv;
            zg += sm[OFF_W2 + 2*HID  + k] * hvv;
            zo += sm[OFF_W2 + 3*HID  + k] * hvv;
        }
        float i2 = fsig  (zi + l2b[0] + l2w[0] * h2);
        float f2 = fsig  (zf + l2b[1] + l2w[1] * h2);
        float g2v= ftanh_(zg + l2b[2] + l2w[2] * h2);
        float o2 = fsig  (zo + l2b[3] + l2w[3] * h2);
        c2 = f2 * c2 + i2 * g2v;
        h2 = o2 * ftanh_(c2);
        sum_h2 += h2;

        float agg = sum_h2 * (1.0f / TT);
        float mu  = W_mu[0] * agg + b_mu[0];
        float lv  = W_lv[0] * agg + b_lv[0];
        float sg  = __expf(0.5f * lv);
        int b = start + hs;
        out[b]           = mu - 1.96f * sg;
        out[BATCH + b]   = mu;
        out[2*BATCH + b] = mu + 1.96f * sg;
        out[3*BATCH + b] = lv;
    }
}

extern "C" void kernel_launch(void* const* d_in, const int* in_sizes, int n_in,
                              void* d_out, int out_size) {
    const float* x     = (const float*)d_in[0];
    const float* W_ih1 = (const float*)d_in[1];
    const float* W_hh1 = (const float*)d_in[2];
    const float* b_ih1 = (const float*)d_in[3];
    const float* b_hh1 = (const float*)d_in[4];
    const float* W_ih2 = (const float*)d_in[5];
    const float* W_hh2 = (const float*)d_in[6];
    const float* b_ih2 = (const float*)d_in[7];
    const float* b_hh2 = (const float*)d_in[8];
    const float* W_mu  = (const float*)d_in[9];
    const float* b_mu  = (const float*)d_in[10];
    const float* W_lv  = (const float*)d_in[11];
    const float* b_lv  = (const float*)d_in[12];
    float* out = (float*)d_out;

    cudaFuncSetAttribute(lstm_v14_kernel,
                         cudaFuncAttributeMaxDynamicSharedMemorySize, SMEM_BYTES);
    lstm_v14_kernel<<<NBLK, NTHR, SMEM_BYTES>>>(x, W_ih1, W_hh1, b_ih1, b_hh1,
                                                W_ih2, W_hh2, b_ih2, b_hh2,
                                                W_mu, b_mu, W_lv, b_lv, out);
}